// round 1
// baseline (speedup 1.0000x reference)
#include <cuda_runtime.h>
#include <cuda_bf16.h>
#include <cstdint>

// Problem constants
#define OFFSET   2
#define EPSILONF 0.01f
#define NUM_EMB  2050      // 2048 + OFFSET
#define EMB_D    2048
#define NUM_PAR  8
#define BATCH    8
#define SEQ      2048

// Scratch for computed positions (no device allocation allowed)
__device__ int d_positions[BATCH * SEQ];

// ---------------------------------------------------------------------------
// Kernel 1: per-batch inclusive cumsum of the mask -> positions
// positions[b][s] = cumsum(mask[b])[s] * mask[b][s] - 1 + OFFSET
// One block per batch row, 1024 threads, 2 elements per thread.
// ---------------------------------------------------------------------------
__global__ void positions_kernel(const int* __restrict__ mask)
{
    const int b = blockIdx.x;
    const int t = threadIdx.x;
    const int* m = mask + (size_t)b * SEQ;

    __shared__ int sh[1024];

    const int m0 = m[2 * t + 0];
    const int m1 = m[2 * t + 1];
    const int pair = m0 + m1;

    sh[t] = pair;
    __syncthreads();

    // Hillis-Steele inclusive scan over 1024 pair-sums
    #pragma unroll
    for (int off = 1; off < 1024; off <<= 1) {
        int v = 0;
        if (t >= off) v = sh[t - off];
        __syncthreads();
        if (t >= off) sh[t] += v;
        __syncthreads();
    }

    const int excl = sh[t] - pair;           // exclusive prefix before this pair
    const int c0 = excl + m0;                // inclusive cumsum at 2t
    const int c1 = excl + m0 + m1;           // inclusive cumsum at 2t+1

    d_positions[b * SEQ + 2 * t + 0] = c0 * m0 - 1 + OFFSET;
    d_positions[b * SEQ + 2 * t + 1] = c1 * m1 - 1 + OFFSET;
}

// ---------------------------------------------------------------------------
// Kernel 2: gather + axpy
// out[p][b][s][d] = weight[pos[b][s]][d] + EPS * mu[p][pos[b][s]][d]
// One block per (b,s) row: 512 threads x float4 covers EMB_D=2048.
// Weight row is read once into registers, reused for all 8 p.
// Output stored with streaming hint (__stcs) to keep L2 for the mu table
// (134 MB, nearly fits the 126 MB L2).
// ---------------------------------------------------------------------------
__global__ __launch_bounds__(512, 4)
void gather_add_kernel(const float4* __restrict__ weight4,
                       const float4* __restrict__ mu4,
                       float4* __restrict__ out4)
{
    const int bs  = blockIdx.x;              // b*SEQ + s, 0..16383
    const int t   = threadIdx.x;             // 0..511  (d/4)
    const int pos = d_positions[bs];

    const int D4 = EMB_D / 4;                // 512

    // Weight row chunk (reused 8x)
    const float4 w = __ldg(&weight4[(size_t)pos * D4 + t]);

    const size_t out_row   = (size_t)bs * D4 + t;     // offset within one p-slab
    const size_t p_stride  = (size_t)BATCH * SEQ * D4; // floats4 per p-slab
    const size_t mu_stride = (size_t)NUM_EMB * D4;     // floats4 per mu p-slab
    const size_t mu_row    = (size_t)pos * D4 + t;

    #pragma unroll
    for (int p = 0; p < NUM_PAR; p++) {
        const float4 m = __ldg(&mu4[(size_t)p * mu_stride + mu_row]);
        float4 o;
        o.x = fmaf(EPSILONF, m.x, w.x);
        o.y = fmaf(EPSILONF, m.y, w.y);
        o.z = fmaf(EPSILONF, m.z, w.z);
        o.w = fmaf(EPSILONF, m.w, w.w);
        __stcs(&out4[(size_t)p * p_stride + out_row], o);
    }
}

// ---------------------------------------------------------------------------
// Launch
// Inputs (metadata order): attention_mask (int), past_key_values_length (0),
//                          weight (f32), mu (f32)
// Output: float32, (NUM_PAR, BATCH, SEQ, EMB_D)
// ---------------------------------------------------------------------------
extern "C" void kernel_launch(void* const* d_in, const int* in_sizes, int n_in,
                              void* d_out, int out_size)
{
    const int*    mask   = (const int*)d_in[0];
    // d_in[1] = past_key_values_length, always 0 in this problem
    const float4* weight = (const float4*)d_in[2];
    const float4* mu     = (const float4*)d_in[3];
    float4*       out    = (float4*)d_out;

    positions_kernel<<<BATCH, 1024>>>(mask);
    gather_add_kernel<<<BATCH * SEQ, 512>>>(weight, mu, out);
}

// round 4
// speedup vs baseline: 1.3221x; 1.3221x over previous
#include <cuda_runtime.h>
#include <cuda_bf16.h>
#include <cstdint>

// Problem constants
#define OFFSET   2
#define EPSILONF 0.01f
#define NUM_EMB  2050      // 2048 + OFFSET
#define EMB_D    2048
#define NUM_PAR  8
#define BATCH    8
#define SEQ      2048

// Scratch for computed positions (no device allocation allowed)
__device__ int d_positions[BATCH * SEQ];

// ---------------------------------------------------------------------------
// Kernel 1: per-batch inclusive cumsum of the mask -> positions
// positions[b][s] = cumsum(mask[b])[s] * mask[b][s] - 1 + OFFSET
// One block per batch row, 1024 threads, 2 elements per thread.
// Warp-shuffle scan: 2 barriers instead of 20.
// ---------------------------------------------------------------------------
__global__ void positions_kernel(const int* __restrict__ mask)
{
    const int b    = blockIdx.x;
    const int t    = threadIdx.x;          // 0..1023
    const int lane = t & 31;
    const int wid  = t >> 5;               // 0..31
    const int* m   = mask + (size_t)b * SEQ;

    const int m0   = m[2 * t + 0];
    const int m1   = m[2 * t + 1];
    const int pair = m0 + m1;

    // Warp-level inclusive scan of pair
    int v = pair;
    #pragma unroll
    for (int off = 1; off < 32; off <<= 1) {
        int u = __shfl_up_sync(0xFFFFFFFFu, v, off);
        if (lane >= off) v += u;
    }

    __shared__ int warp_sums[32];
    if (lane == 31) warp_sums[wid] = v;
    __syncthreads();

    // Warp 0 scans the 32 warp totals
    if (wid == 0) {
        int w = warp_sums[lane];
        #pragma unroll
        for (int off = 1; off < 32; off <<= 1) {
            int u = __shfl_up_sync(0xFFFFFFFFu, w, off);
            if (lane >= off) w += u;
        }
        warp_sums[lane] = w;
    }
    __syncthreads();

    const int base = (wid > 0) ? warp_sums[wid - 1] : 0;
    const int incl = base + v;             // inclusive cumsum of pairs up to t
    const int excl = incl - pair;          // exclusive prefix before this pair

    const int c0 = excl + m0;              // inclusive cumsum at element 2t
    const int c1 = excl + m0 + m1;         // inclusive cumsum at element 2t+1

    d_positions[b * SEQ + 2 * t + 0] = c0 * m0 - 1 + OFFSET;
    d_positions[b * SEQ + 2 * t + 1] = c1 * m1 - 1 + OFFSET;
}

// ---------------------------------------------------------------------------
// Kernel 2: gather + axpy, s-major for cross-batch L2 reuse.
// One block per s. Inside: loop b (8) x p (8).
// Concurrent blocks cover a narrow band of s, so pos[b][s] across ALL batches
// lands in a small band of mu/weight rows (~25 MB working set << 126 MB L2);
// the 8x cross-batch reuse of each row is captured in-wave instead of being
// re-fetched from HBM per batch.
// Output is written with __stcs (streaming) so the 1 GiB of stores never
// evicts the gather tables from L2.
// ---------------------------------------------------------------------------
__global__ __launch_bounds__(512, 3)
void gather_add_kernel(const float4* __restrict__ weight4,
                       const float4* __restrict__ mu4,
                       float4* __restrict__ out4)
{
    const int s = blockIdx.x;              // 0..SEQ-1
    const int t = threadIdx.x;             // 0..511  (d/4)

    const int    D4        = EMB_D / 4;                 // 512
    const size_t p_stride  = (size_t)BATCH * SEQ * D4;  // float4s per out p-slab
    const size_t mu_stride = (size_t)NUM_EMB * D4;      // float4s per mu p-slab

    // Positions for this s across all batches
    int pos[BATCH];
    #pragma unroll
    for (int b = 0; b < BATCH; b++)
        pos[b] = d_positions[b * SEQ + s];

    for (int b = 0; b < BATCH; b++) {
        const size_t row    = (size_t)pos[b] * D4 + t;
        const float4 w      = __ldg(&weight4[row]);
        const size_t out_bs = ((size_t)b * SEQ + s) * D4 + t;

        #pragma unroll
        for (int p = 0; p < NUM_PAR; p++) {
            const float4 m = __ldg(&mu4[(size_t)p * mu_stride + row]);
            float4 o;
            o.x = fmaf(EPSILONF, m.x, w.x);
            o.y = fmaf(EPSILONF, m.y, w.y);
            o.z = fmaf(EPSILONF, m.z, w.z);
            o.w = fmaf(EPSILONF, m.w, w.w);
            __stcs(&out4[(size_t)p * p_stride + out_bs], o);
        }
    }
}

// ---------------------------------------------------------------------------
// Launch
// Inputs (metadata order): attention_mask (int), past_key_values_length (0),
//                          weight (f32), mu (f32)
// Output: float32, (NUM_PAR, BATCH, SEQ, EMB_D)
// ---------------------------------------------------------------------------
extern "C" void kernel_launch(void* const* d_in, const int* in_sizes, int n_in,
                              void* d_out, int out_size)
{
    const int*    mask   = (const int*)d_in[0];
    // d_in[1] = past_key_values_length, always 0 in this problem
    const float4* weight = (const float4*)d_in[2];
    const float4* mu     = (const float4*)d_in[3];
    float4*       out    = (float4*)d_out;

    positions_kernel<<<BATCH, 1024>>>(mask);
    gather_add_kernel<<<SEQ, 512>>>(weight, mu, out);
}

// round 6
// speedup vs baseline: 1.3868x; 1.0490x over previous
#include <cuda_runtime.h>
#include <cuda_bf16.h>
#include <cstdint>

// Problem constants
#define OFFSET   2
#define EPSILONF 0.01f
#define NUM_EMB  2050      // 2048 + OFFSET
#define EMB_D    2048
#define NUM_PAR  8
#define BATCH    8
#define SEQ      2048

// Scratch for computed positions (no device allocation allowed)
__device__ int d_positions[BATCH * SEQ];

// ---------------------------------------------------------------------------
// Kernel 1: per-batch inclusive cumsum of the mask -> positions
// positions[b][s] = cumsum(mask[b])[s] * mask[b][s] - 1 + OFFSET
// One block per batch row, 1024 threads, 2 elements per thread.
// Warp-shuffle scan: 2 barriers total.
// ---------------------------------------------------------------------------
__global__ void positions_kernel(const int* __restrict__ mask)
{
    const int b    = blockIdx.x;
    const int t    = threadIdx.x;          // 0..1023
    const int lane = t & 31;
    const int wid  = t >> 5;               // 0..31
    const int* m   = mask + (size_t)b * SEQ;

    const int m0   = m[2 * t + 0];
    const int m1   = m[2 * t + 1];
    const int pair = m0 + m1;

    // Warp-level inclusive scan of pair
    int v = pair;
    #pragma unroll
    for (int off = 1; off < 32; off <<= 1) {
        int u = __shfl_up_sync(0xFFFFFFFFu, v, off);
        if (lane >= off) v += u;
    }

    __shared__ int warp_sums[32];
    if (lane == 31) warp_sums[wid] = v;
    __syncthreads();

    // Warp 0 scans the 32 warp totals
    if (wid == 0) {
        int w = warp_sums[lane];
        #pragma unroll
        for (int off = 1; off < 32; off <<= 1) {
            int u = __shfl_up_sync(0xFFFFFFFFu, w, off);
            if (lane >= off) w += u;
        }
        warp_sums[lane] = w;
    }
    __syncthreads();

    const int base = (wid > 0) ? warp_sums[wid - 1] : 0;
    const int incl = base + v;             // inclusive cumsum of pairs up to t
    const int excl = incl - pair;          // exclusive prefix before this pair

    const int c0 = excl + m0;              // inclusive at element 2t
    const int c1 = excl + m0 + m1;         // inclusive at element 2t+1

    d_positions[b * SEQ + 2 * t + 0] = c0 * m0 - 1 + OFFSET;
    d_positions[b * SEQ + 2 * t + 1] = c1 * m1 - 1 + OFFSET;
}

// ---------------------------------------------------------------------------
// Kernel 2: gather + axpy.
// One block per (s, b) pair, with b in the LOW bits of blockIdx.x:
//   - 16384 blocks -> full concurrency / latency hiding (R1-level MLP)
//   - concurrent waves span a ~55-wide s band x all 8 batches, so the
//     cross-batch reuse of each mu/weight row still hits L2 in-wave
//     (the R2 traffic win is preserved).
// Lean body: 1 weight load into registers, 8 independent mu loads,
// 8 streaming stores (__stcs keeps the 1 GiB output out of L2).
// ---------------------------------------------------------------------------
__global__ __launch_bounds__(512, 4)
void gather_add_kernel(const float4* __restrict__ weight4,
                       const float4* __restrict__ mu4,
                       float4* __restrict__ out4)
{
    const int bid = blockIdx.x;            // s*BATCH + b
    const int s   = bid >> 3;
    const int b   = bid & 7;
    const int t   = threadIdx.x;           // 0..511  (d/4)

    const int    D4        = EMB_D / 4;                 // 512
    const size_t p_stride  = (size_t)BATCH * SEQ * D4;  // float4s per out p-slab
    const size_t mu_stride = (size_t)NUM_EMB * D4;      // float4s per mu p-slab

    const int    pos    = d_positions[b * SEQ + s];
    const size_t row    = (size_t)pos * D4 + t;
    const float4 w      = __ldg(&weight4[row]);
    const size_t out_bs = ((size_t)b * SEQ + s) * D4 + t;

    #pragma unroll
    for (int p = 0; p < NUM_PAR; p++) {
        const float4 m = __ldg(&mu4[(size_t)p * mu_stride + row]);
        float4 o;
        o.x = fmaf(EPSILONF, m.x, w.x);
        o.y = fmaf(EPSILONF, m.y, w.y);
        o.z = fmaf(EPSILONF, m.z, w.z);
        o.w = fmaf(EPSILONF, m.w, w.w);
        __stcs(&out4[(size_t)p * p_stride + out_bs], o);
    }
}

// ---------------------------------------------------------------------------
// Launch
// Inputs (metadata order): attention_mask (int), past_key_values_length (0),
//                          weight (f32), mu (f32)
// Output: float32, (NUM_PAR, BATCH, SEQ, EMB_D)
// ---------------------------------------------------------------------------
extern "C" void kernel_launch(void* const* d_in, const int* in_sizes, int n_in,
                              void* d_out, int out_size)
{
    const int*    mask   = (const int*)d_in[0];
    // d_in[1] = past_key_values_length, always 0 in this problem
    const float4* weight = (const float4*)d_in[2];
    const float4* mu     = (const float4*)d_in[3];
    float4*       out    = (float4*)d_out;

    positions_kernel<<<BATCH, 1024>>>(mask);
    gather_add_kernel<<<SEQ * BATCH, 512>>>(weight, mu, out);
}

// round 8
// speedup vs baseline: 1.3965x; 1.0070x over previous
#include <cuda_runtime.h>
#include <cuda_bf16.h>
#include <cstdint>

// Problem constants
#define OFFSET   2
#define EPSILONF 0.01f
#define NUM_EMB  2050      // 2048 + OFFSET
#define EMB_D    2048
#define NUM_PAR  8
#define BATCH    8
#define SEQ      2048

// Scratch for computed positions (no device allocation allowed)
__device__ int d_positions[BATCH * SEQ];

// ---------------------------------------------------------------------------
// Kernel 1: per-batch inclusive cumsum of the mask -> positions
// positions[b][s] = cumsum(mask[b])[s] * mask[b][s] - 1 + OFFSET
// One block per batch row, 1024 threads, 2 elements per thread.
// Warp-shuffle scan: 2 barriers total.
// ---------------------------------------------------------------------------
__global__ void positions_kernel(const int* __restrict__ mask)
{
    const int b    = blockIdx.x;
    const int t    = threadIdx.x;          // 0..1023
    const int lane = t & 31;
    const int wid  = t >> 5;               // 0..31
    const int* m   = mask + (size_t)b * SEQ;

    const int m0   = m[2 * t + 0];
    const int m1   = m[2 * t + 1];
    const int pair = m0 + m1;

    // Warp-level inclusive scan of pair
    int v = pair;
    #pragma unroll
    for (int off = 1; off < 32; off <<= 1) {
        int u = __shfl_up_sync(0xFFFFFFFFu, v, off);
        if (lane >= off) v += u;
    }

    __shared__ int warp_sums[32];
    if (lane == 31) warp_sums[wid] = v;
    __syncthreads();

    // Warp 0 scans the 32 warp totals
    if (wid == 0) {
        int w = warp_sums[lane];
        #pragma unroll
        for (int off = 1; off < 32; off <<= 1) {
            int u = __shfl_up_sync(0xFFFFFFFFu, w, off);
            if (lane >= off) w += u;
        }
        warp_sums[lane] = w;
    }
    __syncthreads();

    const int base = (wid > 0) ? warp_sums[wid - 1] : 0;
    const int incl = base + v;             // inclusive cumsum of pairs up to t
    const int excl = incl - pair;          // exclusive prefix before this pair

    const int c0 = excl + m0;              // inclusive at element 2t
    const int c1 = excl + m0 + m1;         // inclusive at element 2t+1

    d_positions[b * SEQ + 2 * t + 0] = c0 * m0 - 1 + OFFSET;
    d_positions[b * SEQ + 2 * t + 1] = c1 * m1 - 1 + OFFSET;
}

// ---------------------------------------------------------------------------
// Kernel 2: gather + axpy.
// One block per (s, b) pair, with b in the LOW bits of blockIdx.x:
//   - 16384 blocks -> full concurrency / latency hiding
//   - concurrent waves span a ~55-wide s band x all 8 batches, so the
//     cross-batch reuse of each mu/weight row hits L2 in-wave.
// A/B vs R6: plain stores instead of __stcs. Each warp STG.128 fully covers
// 4 L2 lines, so lines are fully dirty immediately; evict-first bought
// nothing and its aggressive writeback may be what held DRAM at 78.6%.
// The hot read set (~25 MB, re-touched 64x per wave) should survive LRU
// against the streaming output.
// ---------------------------------------------------------------------------
__global__ __launch_bounds__(512, 4)
void gather_add_kernel(const float4* __restrict__ weight4,
                       const float4* __restrict__ mu4,
                       float4* __restrict__ out4)
{
    const int bid = blockIdx.x;            // s*BATCH + b
    const int s   = bid >> 3;
    const int b   = bid & 7;
    const int t   = threadIdx.x;           // 0..511  (d/4)

    const int    D4        = EMB_D / 4;                 // 512
    const size_t p_stride  = (size_t)BATCH * SEQ * D4;  // float4s per out p-slab
    const size_t mu_stride = (size_t)NUM_EMB * D4;      // float4s per mu p-slab

    const int    pos    = d_positions[b * SEQ + s];
    const size_t row    = (size_t)pos * D4 + t;
    const float4 w      = __ldg(&weight4[row]);
    const size_t out_bs = ((size_t)b * SEQ + s) * D4 + t;

    #pragma unroll
    for (int p = 0; p < NUM_PAR; p++) {
        const float4 m = __ldg(&mu4[(size_t)p * mu_stride + row]);
        float4 o;
        o.x = fmaf(EPSILONF, m.x, w.x);
        o.y = fmaf(EPSILONF, m.y, w.y);
        o.z = fmaf(EPSILONF, m.z, w.z);
        o.w = fmaf(EPSILONF, m.w, w.w);
        out4[(size_t)p * p_stride + out_bs] = o;
    }
}

// ---------------------------------------------------------------------------
// Launch
// Inputs (metadata order): attention_mask (int), past_key_values_length (0),
//                          weight (f32), mu (f32)
// Output: float32, (NUM_PAR, BATCH, SEQ, EMB_D)
// ---------------------------------------------------------------------------
extern "C" void kernel_launch(void* const* d_in, const int* in_sizes, int n_in,
                              void* d_out, int out_size)
{
    const int*    mask   = (const int*)d_in[0];
    // d_in[1] = past_key_values_length, always 0 in this problem
    const float4* weight = (const float4*)d_in[2];
    const float4* mu     = (const float4*)d_in[3];
    float4*       out    = (float4*)d_out;

    positions_kernel<<<BATCH, 1024>>>(mask);
    gather_add_kernel<<<SEQ * BATCH, 512>>>(weight, mu, out);
}

// round 9
// speedup vs baseline: 1.4010x; 1.0032x over previous
#include <cuda_runtime.h>
#include <cuda_bf16.h>
#include <cstdint>

// Problem constants
#define OFFSET   2
#define EPSILONF 0.01f
#define NUM_EMB  2050      // 2048 + OFFSET
#define EMB_D    2048
#define NUM_PAR  8
#define BATCH    8
#define SEQ      2048

// ---------------------------------------------------------------------------
// Single fused kernel: per-block position recompute + gather + axpy.
//
// One block per (s, b) pair, b in the LOW bits of blockIdx.x (cross-batch L2
// reuse in-wave, as established in R2/R5).
//
// Position: instead of a separate scan kernel (+launch gap, ~3.2 us), each
// block recomputes cumsum(mask[b])[0..s] itself. 512 threads x int4 = the
// whole 2048-wide mask row in ONE load per thread; predicated sum + block
// reduce (2 barriers). mask is 64 KB -> L2-resident, so the redundant reads
// are L2 hits (~64 MB over the run, noise at L2=58.6%).
//   pos = cumsum_inclusive * mask[s] - 1 + OFFSET
//
// Main loop unchanged from R8 (at the compulsory-traffic floor): 1 weight
// load, 8 independent mu loads, 8 plain float4 stores (A/B showed __stcs
// is neutral).
// ---------------------------------------------------------------------------
__global__ __launch_bounds__(512, 4)
void fused_embed_kernel(const int4*   __restrict__ mask4,
                        const float4* __restrict__ weight4,
                        const float4* __restrict__ mu4,
                        float4*       __restrict__ out4)
{
    const int bid  = blockIdx.x;           // s*BATCH + b
    const int s    = bid >> 3;
    const int b    = bid & 7;
    const int t    = threadIdx.x;          // 0..511
    const int lane = t & 31;
    const int wid  = t >> 5;               // 0..15

    // ---- positions: block-wide masked sum of mask[b][0..s] ----
    const int4 mv = __ldg(&mask4[b * (SEQ / 4) + t]);  // elements 4t..4t+3

    const int e0 = 4 * t;
    int partial;
    if (e0 + 3 <= s) {
        partial = mv.x + mv.y + mv.z + mv.w;           // fully included
    } else {
        partial = 0;
        if (e0 + 0 <= s) partial += mv.x;
        if (e0 + 1 <= s) partial += mv.y;
        if (e0 + 2 <= s) partial += mv.z;
        if (e0 + 3 <= s) partial += mv.w;
    }

    __shared__ int sh_warp[16];
    __shared__ int sh_ms;

    // the thread owning element s records mask[b][s]
    if ((s >> 2) == t) {
        const int j = s & 3;
        sh_ms = (j == 0) ? mv.x : (j == 1) ? mv.y : (j == 2) ? mv.z : mv.w;
    }

    // warp reduce
    #pragma unroll
    for (int off = 16; off > 0; off >>= 1)
        partial += __shfl_down_sync(0xFFFFFFFFu, partial, off);
    if (lane == 0) sh_warp[wid] = partial;
    __syncthreads();

    if (wid == 0) {
        int v = (lane < 16) ? sh_warp[lane] : 0;
        #pragma unroll
        for (int off = 8; off > 0; off >>= 1)
            v += __shfl_down_sync(0xFFFFFFFFu, v, off);
        if (lane == 0) sh_warp[0] = v;
    }
    __syncthreads();

    const int incl = sh_warp[0];                       // cumsum(mask)[s]
    const int pos  = incl * sh_ms - 1 + OFFSET;        // = incl*m_s + 1

    // ---- gather + axpy ----
    const int    D4        = EMB_D / 4;                 // 512
    const size_t p_stride  = (size_t)BATCH * SEQ * D4;  // float4s per out p-slab
    const size_t mu_stride = (size_t)NUM_EMB * D4;      // float4s per mu p-slab

    const size_t row    = (size_t)pos * D4 + t;
    const float4 w      = __ldg(&weight4[row]);
    const size_t out_bs = ((size_t)b * SEQ + s) * D4 + t;

    #pragma unroll
    for (int p = 0; p < NUM_PAR; p++) {
        const float4 m = __ldg(&mu4[(size_t)p * mu_stride + row]);
        float4 o;
        o.x = fmaf(EPSILONF, m.x, w.x);
        o.y = fmaf(EPSILONF, m.y, w.y);
        o.z = fmaf(EPSILONF, m.z, w.z);
        o.w = fmaf(EPSILONF, m.w, w.w);
        out4[(size_t)p * p_stride + out_bs] = o;
    }
}

// ---------------------------------------------------------------------------
// Launch
// Inputs (metadata order): attention_mask (int), past_key_values_length (0),
//                          weight (f32), mu (f32)
// Output: float32, (NUM_PAR, BATCH, SEQ, EMB_D)
// ---------------------------------------------------------------------------
extern "C" void kernel_launch(void* const* d_in, const int* in_sizes, int n_in,
                              void* d_out, int out_size)
{
    const int4*   mask   = (const int4*)d_in[0];
    // d_in[1] = past_key_values_length, always 0 in this problem
    const float4* weight = (const float4*)d_in[2];
    const float4* mu     = (const float4*)d_in[3];
    float4*       out    = (float4*)d_out;

    fused_embed_kernel<<<SEQ * BATCH, 512>>>(mask, weight, mu, out);
}

// round 11
// speedup vs baseline: 1.4180x; 1.0122x over previous
#include <cuda_runtime.h>
#include <cuda_bf16.h>
#include <cstdint>

// Problem constants
#define OFFSET   2
#define EPSILONF 0.01f
#define NUM_EMB  2050      // 2048 + OFFSET
#define EMB_D    2048
#define NUM_PAR  8
#define BATCH    8
#define SEQ      2048

// ---------------------------------------------------------------------------
// Single fused kernel: per-block position recompute + gather + axpy.
//
// One block per (s, b), b in the LOW bits of blockIdx.x (cross-batch L2 reuse
// in-wave). Main loop is at the compulsory-traffic floor (R8 A/B: __stcs
// neutral); this round attacks the position-prologue cost:
//   - only threads covering elements <= s load the mask (avg 50% fewer loads)
//   - REDUX.SUM warp reduce (1 instr vs 5-shuffle tree)
//   - ONE barrier: leaders write warp sums, then every thread sums the 16
//     values from shared itself (broadcast LDS), instead of a second
//     reduce+barrier round-trip.
// ---------------------------------------------------------------------------
__global__ __launch_bounds__(512, 4)
void fused_embed_kernel(const int4*   __restrict__ mask4,
                        const float4* __restrict__ weight4,
                        const float4* __restrict__ mu4,
                        float4*       __restrict__ out4)
{
    const int bid  = blockIdx.x;           // s*BATCH + b
    const int s    = bid >> 3;
    const int b    = bid & 7;
    const int t    = threadIdx.x;          // 0..511
    const int lane = t & 31;
    const int wid  = t >> 5;               // 0..15

    __shared__ int sh_warp[16];
    __shared__ int sh_ms;

    // ---- masked prefix sum of mask[b][0..s] (scalar per block) ----
    const int owner = s >> 2;              // thread owning element s
    int partial = 0;
    if (t <= owner) {
        const int4 mv = __ldg(&mask4[b * (SEQ / 4) + t]);  // elems 4t..4t+3
        if (t < owner) {
            partial = mv.x + mv.y + mv.z + mv.w;           // fully included
        } else {
            const int j = s & 3;                           // tail thread
            partial = mv.x;
            if (j >= 1) partial += mv.y;
            if (j >= 2) partial += mv.z;
            if (j >= 3) partial += mv.w;
            sh_ms = (j == 0) ? mv.x : (j == 1) ? mv.y : (j == 2) ? mv.z : mv.w;
        }
    }

    partial = __reduce_add_sync(0xFFFFFFFFu, partial);     // REDUX.SUM
    if (lane == 0) sh_warp[wid] = partial;
    __syncthreads();

    int incl = 0;                                          // cumsum(mask)[s]
    #pragma unroll
    for (int i = 0; i < 16; i++) incl += sh_warp[i];       // broadcast LDS

    const int pos = incl * sh_ms - 1 + OFFSET;

    // ---- gather + axpy ----
    const int    D4        = EMB_D / 4;                 // 512
    const size_t p_stride  = (size_t)BATCH * SEQ * D4;  // float4s per out p-slab
    const size_t mu_stride = (size_t)NUM_EMB * D4;      // float4s per mu p-slab

    const size_t row    = (size_t)pos * D4 + t;
    const float4 w      = __ldg(&weight4[row]);
    const size_t out_bs = ((size_t)b * SEQ + s) * D4 + t;

    #pragma unroll
    for (int p = 0; p < NUM_PAR; p++) {
        const float4 m = __ldg(&mu4[(size_t)p * mu_stride + row]);
        float4 o;
        o.x = fmaf(EPSILONF, m.x, w.x);
        o.y = fmaf(EPSILONF, m.y, w.y);
        o.z = fmaf(EPSILONF, m.z, w.z);
        o.w = fmaf(EPSILONF, m.w, w.w);
        out4[(size_t)p * p_stride + out_bs] = o;
    }
}

// ---------------------------------------------------------------------------
// Launch
// Inputs (metadata order): attention_mask (int), past_key_values_length (0),
//                          weight (f32), mu (f32)
// Output: float32, (NUM_PAR, BATCH, SEQ, EMB_D)
// ---------------------------------------------------------------------------
extern "C" void kernel_launch(void* const* d_in, const int* in_sizes, int n_in,
                              void* d_out, int out_size)
{
    const int4*   mask   = (const int4*)d_in[0];
    // d_in[1] = past_key_values_length, always 0 in this problem
    const float4* weight = (const float4*)d_in[2];
    const float4* mu     = (const float4*)d_in[3];
    float4*       out    = (float4*)d_out;

    fused_embed_kernel<<<SEQ * BATCH, 512>>>(mask, weight, mu, out);
}

// round 14
// speedup vs baseline: 1.4188x; 1.0005x over previous
#include <cuda_runtime.h>
#include <cuda_bf16.h>
#include <cstdint>

// Problem constants
#define OFFSET   2
#define EPSILONF 0.01f
#define NUM_EMB  2050      // 2048 + OFFSET
#define EMB_D    2048
#define NUM_PAR  8
#define BATCH    8
#define SEQ      2048

// ---------------------------------------------------------------------------
// Fused kernel, two s-positions per block.
//
// Block = (s_pair i, b), b in LOW bits of blockIdx.x (cross-batch L2 reuse
// in-wave, established R2/R5). 1024 threads: warps 0..15 stream row s0=2i,
// warps 16..31 stream row s1=2i+1.
//
// Prologue amortization: cumsum[s1] determines BOTH positions
// (cumsum[s0] = cumsum[s1] - mask[s1]), and since s1 is odd, mask[s0] and
// mask[s1] live in the same int4 word. One reduce (same cost as the
// single-row version) now serves 2 rows -> prologue work and barriers per
// output byte halve vs R10.
//
// Main loop per thread identical to R10 (compulsory-traffic floor; R8 A/B
// showed __stcs neutral): 1 weight load, 8 independent mu loads, 8 stores.
// ---------------------------------------------------------------------------
__global__ __launch_bounds__(1024, 2)
void fused_embed_kernel(const int4*   __restrict__ mask4,
                        const float4* __restrict__ weight4,
                        const float4* __restrict__ mu4,
                        float4*       __restrict__ out4)
{
    const int bid  = blockIdx.x;            // i*BATCH + b
    const int i    = bid >> 3;              // s pair index, 0..1023
    const int b    = bid & 7;
    const int t    = threadIdx.x;           // 0..1023
    const int half = t >> 9;                // 0 -> row s0, 1 -> row s1
    const int tt   = t & 511;               // d/4 within row
    const int lane = t & 31;
    const int wid  = t >> 5;                // 0..31

    const int s1 = 2 * i + 1;               // odd
    const int s  = 2 * i + half;            // this half's row

    __shared__ int sh_warp[16];
    __shared__ int sh_m0, sh_m1;

    // ---- one reduce: cumsum(mask[b])[s1], done by warps 0..15 ----
    const int owner = s1 >> 2;               // thread (in half 0) owning s1
    int partial = 0;
    if (half == 0 && tt <= owner) {
        const int4 mv = __ldg(&mask4[b * (SEQ / 4) + tt]);   // elems 4tt..4tt+3
        if (tt < owner) {
            partial = mv.x + mv.y + mv.z + mv.w;
        } else {
            const int j1 = s1 & 3;           // 1 or 3 (s1 odd)
            partial = mv.x + mv.y;           // j1 >= 1 always
            if (j1 == 3) partial += mv.z + mv.w;
            // mask[s0], mask[s1] are adjacent in this same word
            if (j1 == 1) { sh_m0 = mv.x; sh_m1 = mv.y; }
            else         { sh_m0 = mv.z; sh_m1 = mv.w; }
        }
    }

    partial = __reduce_add_sync(0xFFFFFFFFu, partial);       // REDUX.SUM
    if (lane == 0 && wid < 16) sh_warp[wid] = partial;
    __syncthreads();

    int incl1 = 0;                                           // cumsum[s1]
    #pragma unroll
    for (int k = 0; k < 16; k++) incl1 += sh_warp[k];        // broadcast LDS

    const int m0 = sh_m0, m1 = sh_m1;
    const int incl0 = incl1 - m1;                            // cumsum[s0]
    // pos = incl*m - 1 + OFFSET = incl*m + 1
    const int pos = half ? (incl1 * m1 + 1) : (incl0 * m0 + 1);

    // ---- gather + axpy ----
    const int    D4        = EMB_D / 4;                  // 512
    const size_t p_stride  = (size_t)BATCH * SEQ * D4;   // float4s per out p-slab
    const size_t mu_stride = (size_t)NUM_EMB * D4;       // float4s per mu p-slab

    const size_t row    = (size_t)pos * D4 + tt;
    const float4 w      = __ldg(&weight4[row]);
    const size_t out_bs = ((size_t)b * SEQ + s) * D4 + tt;

    #pragma unroll
    for (int p = 0; p < NUM_PAR; p++) {
        const float4 m = __ldg(&mu4[(size_t)p * mu_stride + row]);
        float4 o;
        o.x = fmaf(EPSILONF, m.x, w.x);
        o.y = fmaf(EPSILONF, m.y, w.y);
        o.z = fmaf(EPSILONF, m.z, w.z);
        o.w = fmaf(EPSILONF, m.w, w.w);
        out4[(size_t)p * p_stride + out_bs] = o;
    }
}

// ---------------------------------------------------------------------------
// Launch
// Inputs (metadata order): attention_mask (int), past_key_values_length (0),
//                          weight (f32), mu (f32)
// Output: float32, (NUM_PAR, BATCH, SEQ, EMB_D)
// ---------------------------------------------------------------------------
extern "C" void kernel_launch(void* const* d_in, const int* in_sizes, int n_in,
                              void* d_out, int out_size)
{
    const int4*   mask   = (const int4*)d_in[0];
    // d_in[1] = past_key_values_length, always 0 in this problem
    const float4* weight = (const float4*)d_in[2];
    const float4* mu     = (const float4*)d_in[3];
    float4*       out    = (float4*)d_out;

    fused_embed_kernel<<<(SEQ / 2) * BATCH, 1024>>>(mask, weight, mu, out);
}